// round 12
// baseline (speedup 1.0000x reference)
#include <cuda_runtime.h>
#include <cuda_bf16.h>
#include <cstdint>

// Problem constants
#define B_ 8
#define S_ 1024
#define E_ 1024
#define H_ 16
#define D_ 64
#define ROWS (B_ * S_)          // 8192
#define GROUPS (B_ * H_)        // 128
#define GCHUNK (S_ * D_)        // 65536
#define FULL 0xffffffffu

// Scratch (device globals; allocation is forbidden)
__device__ uint32_t g_qb[ROWS * E_];     // Q, tf32 bits
__device__ uint32_t g_kb[ROWS * E_];     // K, tf32 bits
__device__ uint32_t g_vb[ROWS * E_];     // V, tf32 bits
__device__ uint32_t g_attb[ROWS * E_];   // attention output, tf32 bits
__device__ uint32_t g_x[ROWS * E_];      // hidden_states, tf32 bits
__device__ uint32_t g_wt[4 * E_ * E_];   // transposed weights [N][K], tf32 bits

__device__ __forceinline__ uint32_t f2tf(float x) {
    uint32_t u;
    asm("cvt.rna.tf32.f32 %0, %1;" : "=r"(u) : "f"(x));
    return u;
}

__device__ __forceinline__ void mma_tf32(float c[4], uint32_t a0, uint32_t a1,
                                         uint32_t a2, uint32_t a3,
                                         uint32_t b0, uint32_t b1) {
    asm volatile(
        "mma.sync.aligned.m16n8k8.row.col.f32.tf32.tf32.f32 "
        "{%0,%1,%2,%3},{%4,%5,%6,%7},{%8,%9},{%0,%1,%2,%3};"
        : "+f"(c[0]), "+f"(c[1]), "+f"(c[2]), "+f"(c[3])
        : "r"(a0), "r"(a1), "r"(a2), "r"(a3), "r"(b0), "r"(b1));
}

__device__ __forceinline__ uint32_t smem_u32(const void* p) {
    uint32_t a;
    asm("{ .reg .u64 t; cvta.to.shared.u64 t, %1; cvt.u32.u64 %0, t; }"
        : "=r"(a) : "l"(p));
    return a;
}

__device__ __forceinline__ void cp16(uint32_t dst, const void* src) {
    asm volatile("cp.async.cg.shared.global [%0], [%1], 16;"
                 :: "r"(dst), "l"(src));
}
#define CPCOMMIT() asm volatile("cp.async.commit_group;" ::: "memory")
#define CPWAIT(n)  asm volatile("cp.async.wait_group %0;" :: "n"(n) : "memory")

// ===========================================================================
// Weight transpose + tf32 convert: WT[n][k] = rna_tf32(W[k][n])
// ===========================================================================
__global__ __launch_bounds__(256) void transpose_w(
    const float* __restrict__ w0, const float* __restrict__ w1,
    const float* __restrict__ w2, const float* __restrict__ w3,
    uint32_t* __restrict__ outb)
{
    __shared__ float tile[32][33];
    const float* src = (blockIdx.z == 0) ? w0 : (blockIdx.z == 1) ? w1
                     : (blockIdx.z == 2) ? w2 : w3;
    uint32_t* dst = outb + (size_t)blockIdx.z * E_ * E_;

    const int tx = threadIdx.x, ty = threadIdx.y;
    const int x = blockIdx.x * 32 + tx;
    const int y = blockIdx.y * 32 + ty;
    #pragma unroll
    for (int j = 0; j < 32; j += 8)
        tile[ty + j][tx] = src[(size_t)(y + j) * E_ + x];
    __syncthreads();
    const int ox = blockIdx.y * 32 + tx;
    const int oy = blockIdx.x * 32 + ty;
    #pragma unroll
    for (int j = 0; j < 32; j += 8)
        dst[(size_t)(oy + j) * E_ + ox] = f2tf(tile[tx][ty + j]);
}

// ===========================================================================
// Elementwise fp32 -> tf32 bits (rna)
// ===========================================================================
__global__ __launch_bounds__(256) void convert_x(
    const float* __restrict__ in, uint32_t* __restrict__ out)
{
    const size_t i = ((size_t)blockIdx.x * 256 + threadIdx.x) * 4;
    float4 v = *(const float4*)(in + i);
    uint4 u;
    u.x = f2tf(v.x); u.y = f2tf(v.y); u.z = f2tf(v.z); u.w = f2tf(v.w);
    *(uint4*)(out + i) = u;
}

// ===========================================================================
// Pipelined TF32 mma.sync GEMM. A:[M][K] tf32 bits, Bt:[N][K] tf32 bits.
// BM=128, BN=256, BK=16; 256 threads = 8 warps (2x4), warp tile 64x64.
// 4-stage cp.async pipeline. otf=1 -> tf32-bit output; otf=0 -> fp32 (+bias).
// grid (E/256, ROWS/128, nmat)
// ===========================================================================
#define SK 20
#define ASTG (128 * SK)          // A words per stage (2560)
#define BSTG (256 * SK)          // B words per stage (5120)
#define STGW (ASTG + BSTG)       // words per stage (7680)
#define GSMEM (4 * STGW * 4)     // bytes: 4 stages (122880)

__global__ __launch_bounds__(256, 1) void gemm_tc32(
    const uint32_t* __restrict__ A, const uint32_t* __restrict__ Bt_base,
    const float* __restrict__ bias, int otf,
    float* __restrict__ C0, float* __restrict__ C1, float* __restrict__ C2)
{
    extern __shared__ uint32_t sm[];
    const uint32_t sb = smem_u32(sm);

    const int tid  = threadIdx.x;
    const int lane = tid & 31;
    const int wid  = tid >> 5;
    const int wm   = wid >> 2;          // 0..1  (64-row slab)
    const int wn   = wid & 3;           // 0..3  (64-col slab)
    const int gid  = lane >> 2;         // 0..7
    const int tig  = lane & 3;          // 0..3

    const int bx = blockIdx.x, by = blockIdx.y, bz = blockIdx.z;
    const uint32_t* Bt = Bt_base + (size_t)bz * E_ * E_;
    float* C = (bz == 0) ? C0 : (bz == 1) ? C1 : C2;

    const uint32_t* Ab = A  + (size_t)by * 128 * E_;
    const uint32_t* Bb = Bt + (size_t)bx * 256 * E_;

    const int lr = tid >> 2;            // 0..63
    const int lk = (tid & 3) * 4;       // 0,4,8,12

    float acc[4][8][4];
    #pragma unroll
    for (int i = 0; i < 4; i++)
        #pragma unroll
        for (int j = 0; j < 8; j++)
            #pragma unroll
            for (int f = 0; f < 4; f++) acc[i][j][f] = 0.0f;

    // ---- prologue: stages 0..2 ----
    #pragma unroll
    for (int s = 0; s < 3; s++) {
        const uint32_t ab = sb + (uint32_t)(s * STGW) * 4;
        const uint32_t bbs = ab + ASTG * 4;
        const uint32_t* ag = Ab + (size_t)lr * E_ + s * 16 + lk;
        const uint32_t* bg = Bb + (size_t)lr * E_ + s * 16 + lk;
        cp16(ab  + (uint32_t)(lr * SK + lk) * 4,         ag);
        cp16(ab  + (uint32_t)((lr + 64) * SK + lk) * 4,  ag + (size_t)64 * E_);
        cp16(bbs + (uint32_t)(lr * SK + lk) * 4,         bg);
        cp16(bbs + (uint32_t)((lr + 64) * SK + lk) * 4,  bg + (size_t)64 * E_);
        cp16(bbs + (uint32_t)((lr + 128) * SK + lk) * 4, bg + (size_t)128 * E_);
        cp16(bbs + (uint32_t)((lr + 192) * SK + lk) * 4, bg + (size_t)192 * E_);
        CPCOMMIT();
    }

    for (int c = 0; c < 64; c++) {
        CPWAIT(2);
        __syncthreads();

        if (c + 3 < 64) {
            const int s = (c + 3) & 3;
            const uint32_t ab = sb + (uint32_t)(s * STGW) * 4;
            const uint32_t bbs = ab + ASTG * 4;
            const uint32_t* ag = Ab + (size_t)lr * E_ + (c + 3) * 16 + lk;
            const uint32_t* bg = Bb + (size_t)lr * E_ + (c + 3) * 16 + lk;
            cp16(ab  + (uint32_t)(lr * SK + lk) * 4,         ag);
            cp16(ab  + (uint32_t)((lr + 64) * SK + lk) * 4,  ag + (size_t)64 * E_);
            cp16(bbs + (uint32_t)(lr * SK + lk) * 4,         bg);
            cp16(bbs + (uint32_t)((lr + 64) * SK + lk) * 4,  bg + (size_t)64 * E_);
            cp16(bbs + (uint32_t)((lr + 128) * SK + lk) * 4, bg + (size_t)128 * E_);
            cp16(bbs + (uint32_t)((lr + 192) * SK + lk) * 4, bg + (size_t)192 * E_);
        }
        CPCOMMIT();

        const uint32_t* As = sm + (size_t)(c & 3) * STGW;
        const uint32_t* Bs = As + ASTG;

        #pragma unroll
        for (int s8 = 0; s8 < 2; s8++) {
            const int kb = s8 * 8;
            uint32_t af[4][4], bf[8][2];
            #pragma unroll
            for (int i = 0; i < 4; i++) {
                const int rb = wm * 64 + i * 16;
                af[i][0] = As[(rb + gid) * SK + kb + tig];
                af[i][1] = As[(rb + 8 + gid) * SK + kb + tig];
                af[i][2] = As[(rb + gid) * SK + kb + tig + 4];
                af[i][3] = As[(rb + 8 + gid) * SK + kb + tig + 4];
            }
            #pragma unroll
            for (int j = 0; j < 8; j++) {
                const int cb = wn * 64 + j * 8;
                bf[j][0] = Bs[(cb + gid) * SK + kb + tig];
                bf[j][1] = Bs[(cb + gid) * SK + kb + tig + 4];
            }
            #pragma unroll
            for (int i = 0; i < 4; i++)
                #pragma unroll
                for (int j = 0; j < 8; j++)
                    mma_tf32(acc[i][j], af[i][0], af[i][1], af[i][2], af[i][3],
                             bf[j][0], bf[j][1]);
        }
    }

    // ---- epilogue ----
    #pragma unroll
    for (int i = 0; i < 4; i++) {
        const int row0 = by * 128 + wm * 64 + i * 16 + gid;
        #pragma unroll
        for (int j = 0; j < 8; j++) {
            const int col = bx * 256 + wn * 64 + j * 8 + 2 * tig;
            float2 v0, v1;
            if (otf) {
                v0 = make_float2(__uint_as_float(f2tf(acc[i][j][0])),
                                 __uint_as_float(f2tf(acc[i][j][1])));
                v1 = make_float2(__uint_as_float(f2tf(acc[i][j][2])),
                                 __uint_as_float(f2tf(acc[i][j][3])));
            } else {
                float b0 = 0.0f, b1 = 0.0f;
                if (bias != nullptr) { b0 = bias[col]; b1 = bias[col + 1]; }
                v0 = make_float2(acc[i][j][0] + b0, acc[i][j][1] + b1);
                v1 = make_float2(acc[i][j][2] + b0, acc[i][j][3] + b1);
            }
            *(float2*)(C + (size_t)row0 * E_ + col) = v0;
            *(float2*)(C + (size_t)(row0 + 8) * E_ + col) = v1;
        }
    }
}

// ---------------------------------------------------------------------------
// TF32 tensor-core flash attention with cp.async double-buffered K/V staging.
// Block = 128 threads (4 warps) = 64 query rows; grid (S/64, GROUPS).
// __launch_bounds__(128,3): cap regs at 170 so 3 CTAs/SM fit (smem 3x71.7KB).
// ---------------------------------------------------------------------------
#define KW 68
#define VW 72
#define KVSTG (64 * KW + 64 * VW)
#define ATT_SMEM (2 * KVSTG * 4)

__global__ __launch_bounds__(128, 3) void attn_mma()
{
    extern __shared__ uint32_t ash[];
    const uint32_t sb = smem_u32(ash);

    const int g    = blockIdx.y;
    const int r0   = blockIdx.x * 64;
    const int tid  = threadIdx.x;
    const int lane = tid & 31;
    const int w    = tid >> 5;
    const int gid  = lane >> 2;
    const int tig  = lane & 3;

    const uint32_t* Qb = g_qb + (size_t)g * GCHUNK;
    const uint32_t* Kb = g_kb + (size_t)g * GCHUNK;
    const uint32_t* Vb = g_vb + (size_t)g * GCHUNK;

    // ---- prologue: chunk 0 K/V -> buf0 ; Q -> buf1 K-area ----
    #pragma unroll
    for (int it = 0; it < 8; it++) {
        int slot = tid + it * 128;
        int r  = slot >> 4;
        int c4 = (slot & 15) * 4;
        cp16(sb + (uint32_t)(r * KW + c4) * 4,            Kb + (size_t)r * D_ + c4);
        cp16(sb + (uint32_t)(64 * KW + r * VW + c4) * 4,  Vb + (size_t)r * D_ + c4);
    }
    CPCOMMIT();
    #pragma unroll
    for (int it = 0; it < 8; it++) {
        int slot = tid + it * 128;
        int r  = slot >> 4;
        int c4 = (slot & 15) * 4;
        cp16(sb + (uint32_t)(KVSTG + r * KW + c4) * 4, Qb + (size_t)(r0 + r) * D_ + c4);
    }
    CPCOMMIT();
    CPWAIT(0);
    __syncthreads();

    uint32_t qf[8][4];
    {
        const uint32_t* Qs = ash + KVSTG;
        const int qrow = w * 16;
        #pragma unroll
        for (int kd = 0; kd < 8; kd++) {
            qf[kd][0] = Qs[(qrow + gid) * KW + 8 * kd + tig];
            qf[kd][1] = Qs[(qrow + gid + 8) * KW + 8 * kd + tig];
            qf[kd][2] = Qs[(qrow + gid) * KW + 8 * kd + tig + 4];
            qf[kd][3] = Qs[(qrow + gid + 8) * KW + 8 * kd + tig + 4];
        }
    }
    __syncthreads();

    float oacc[8][4];
    #pragma unroll
    for (int jd = 0; jd < 8; jd++)
        #pragma unroll
        for (int f = 0; f < 4; f++) oacc[jd][f] = 0.0f;

    float m0 = -1e30f, m1 = -1e30f, l0 = 0.0f, l1 = 0.0f;
    const float scale = 0.03125f;

    const int srcbase = lane & ~3;
    const int src0 = srcbase | (tig >> 1);
    const int src2 = src0 + 2;
    const bool hi = tig & 1;

    for (int c = 0; c < 16; c++) {
        if (c > 0) { CPWAIT(0); __syncthreads(); }

        if (c + 1 < 16) {
            const uint32_t dstb = sb + (uint32_t)(((c + 1) & 1) * KVSTG) * 4;
            const int rbase = (c + 1) * 64;
            #pragma unroll
            for (int it = 0; it < 8; it++) {
                int slot = tid + it * 128;
                int r  = slot >> 4;
                int c4 = (slot & 15) * 4;
                cp16(dstb + (uint32_t)(r * KW + c4) * 4,
                     Kb + (size_t)(rbase + r) * D_ + c4);
                cp16(dstb + (uint32_t)(64 * KW + r * VW + c4) * 4,
                     Vb + (size_t)(rbase + r) * D_ + c4);
            }
        }
        CPCOMMIT();

        const uint32_t* Ks = ash + (size_t)(c & 1) * KVSTG;
        const uint32_t* Vs = Ks + 64 * KW;

        float sacc[8][4];
        #pragma unroll
        for (int j = 0; j < 8; j++)
            #pragma unroll
            for (int f = 0; f < 4; f++) sacc[j][f] = 0.0f;

        #pragma unroll
        for (int kd = 0; kd < 8; kd++) {
            uint32_t bf[8][2];
            #pragma unroll
            for (int j = 0; j < 8; j++) {
                bf[j][0] = Ks[(8 * j + gid) * KW + 8 * kd + tig];
                bf[j][1] = Ks[(8 * j + gid) * KW + 8 * kd + tig + 4];
            }
            #pragma unroll
            for (int j = 0; j < 8; j++)
                mma_tf32(sacc[j], qf[kd][0], qf[kd][1], qf[kd][2], qf[kd][3],
                         bf[j][0], bf[j][1]);
        }

        float mx0 = -1e30f, mx1 = -1e30f;
        #pragma unroll
        for (int j = 0; j < 8; j++) {
            sacc[j][0] *= scale; sacc[j][1] *= scale;
            sacc[j][2] *= scale; sacc[j][3] *= scale;
            mx0 = fmaxf(mx0, fmaxf(sacc[j][0], sacc[j][1]));
            mx1 = fmaxf(mx1, fmaxf(sacc[j][2], sacc[j][3]));
        }
        mx0 = fmaxf(mx0, __shfl_xor_sync(FULL, mx0, 1));
        mx0 = fmaxf(mx0, __shfl_xor_sync(FULL, mx0, 2));
        mx1 = fmaxf(mx1, __shfl_xor_sync(FULL, mx1, 1));
        mx1 = fmaxf(mx1, __shfl_xor_sync(FULL, mx1, 2));

        const float nm0 = fmaxf(m0, mx0);
        const float nm1 = fmaxf(m1, mx1);
        const float a0 = __expf(m0 - nm0);
        const float a1 = __expf(m1 - nm1);
        m0 = nm0; m1 = nm1;

        float rs0 = 0.0f, rs1 = 0.0f;
        #pragma unroll
        for (int j = 0; j < 8; j++) {
            sacc[j][0] = __expf(sacc[j][0] - nm0);
            sacc[j][1] = __expf(sacc[j][1] - nm0);
            sacc[j][2] = __expf(sacc[j][2] - nm1);
            sacc[j][3] = __expf(sacc[j][3] - nm1);
            rs0 += sacc[j][0] + sacc[j][1];
            rs1 += sacc[j][2] + sacc[j][3];
        }
        rs0 += __shfl_xor_sync(FULL, rs0, 1);
        rs0 += __shfl_xor_sync(FULL, rs0, 2);
        rs1 += __shfl_xor_sync(FULL, rs1, 1);
        rs1 += __shfl_xor_sync(FULL, rs1, 2);
        l0 = l0 * a0 + rs0;
        l1 = l1 * a1 + rs1;

        #pragma unroll
        for (int jd = 0; jd < 8; jd++) {
            oacc[jd][0] *= a0; oacc[jd][1] *= a0;
            oacc[jd][2] *= a1; oacc[jd][3] *= a1;
        }

        #pragma unroll
        for (int kk = 0; kk < 8; kk++) {
            const float p0 = sacc[kk][0], p1 = sacc[kk][1];
            const float p2 = sacc[kk][2], p3 = sacc[kk][3];
            const float x00 = __shfl_sync(FULL, p0, src0);
            const float x01 = __shfl_sync(FULL, p1, src0);
            const float x20 = __shfl_sync(FULL, p2, src0);
            const float x21 = __shfl_sync(FULL, p3, src0);
            const float y00 = __shfl_sync(FULL, p0, src2);
            const float y01 = __shfl_sync(FULL, p1, src2);
            const float y20 = __shfl_sync(FULL, p2, src2);
            const float y21 = __shfl_sync(FULL, p3, src2);
            const uint32_t af0 = f2tf(hi ? x01 : x00);
            const uint32_t af1 = f2tf(hi ? x21 : x20);
            const uint32_t af2 = f2tf(hi ? y01 : y00);
            const uint32_t af3 = f2tf(hi ? y21 : y20);
            #pragma unroll
            for (int jd = 0; jd < 8; jd++) {
                uint32_t b0 = Vs[(8 * kk + tig) * VW + 8 * jd + gid];
                uint32_t b1 = Vs[(8 * kk + tig + 4) * VW + 8 * jd + gid];
                mma_tf32(oacc[jd], af0, af1, af2, af3, b0, b1);
            }
        }
    }

    const float inv0 = 1.0f / l0;
    const float inv1 = 1.0f / l1;
    const int b = g >> 4, h = g & 15;
    const int row0 = r0 + w * 16 + gid;
    #pragma unroll
    for (int jd = 0; jd < 8; jd++) {
        const int col = h * D_ + 8 * jd + 2 * tig;
        uint2 v0, v1;
        v0.x = f2tf(oacc[jd][0] * inv0);
        v0.y = f2tf(oacc[jd][1] * inv0);
        v1.x = f2tf(oacc[jd][2] * inv1);
        v1.y = f2tf(oacc[jd][3] * inv1);
        *(uint2*)&g_attb[(size_t)(b * S_ + row0) * E_ + col] = v0;
        *(uint2*)&g_attb[(size_t)(b * S_ + row0 + 8) * E_ + col] = v1;
    }
}

// ---------------------------------------------------------------------------
extern "C" void kernel_launch(void* const* d_in, const int* in_sizes, int n_in,
                              void* d_out, int out_size)
{
    const float* hs    = (const float*)d_in[0];
    const float* w_q   = (const float*)d_in[1];
    const float* w_k   = (const float*)d_in[2];
    const float* w_v   = (const float*)d_in[3];
    const float* w_out = (const float*)d_in[4];
    const float* b_out = (const float*)d_in[5];
    float* out = (float*)d_out;

    uint32_t *qp, *kp, *vp, *wtp, *xp, *abp;
    cudaGetSymbolAddress((void**)&qp, g_qb);
    cudaGetSymbolAddress((void**)&kp, g_kb);
    cudaGetSymbolAddress((void**)&vp, g_vb);
    cudaGetSymbolAddress((void**)&abp, g_attb);
    cudaGetSymbolAddress((void**)&xp, g_x);
    cudaGetSymbolAddress((void**)&wtp, g_wt);

    cudaFuncSetAttribute(gemm_tc32, cudaFuncAttributeMaxDynamicSharedMemorySize,
                         GSMEM);
    cudaFuncSetAttribute(attn_mma, cudaFuncAttributeMaxDynamicSharedMemorySize,
                         ATT_SMEM);

    // 1. one-time operand conversion
    transpose_w<<<dim3(32, 32, 4), dim3(32, 8)>>>(w_q, w_k, w_v, w_out, wtp);
    convert_x<<<ROWS * E_ / 1024, 256>>>(hs, xp);

    // 2. fused QKV projections (emit tf32 bits)
    gemm_tc32<<<dim3(E_ / 256, ROWS / 128, 3), 256, GSMEM>>>(
        xp, wtp, nullptr, 1, (float*)qp, (float*)kp, (float*)vp);

    // 3. attention (tf32 in, tf32 bits out)
    attn_mma<<<dim3(S_ / 64, GROUPS), 128, ATT_SMEM>>>();

    // 4. output projection (fp32 out + bias)
    gemm_tc32<<<dim3(E_ / 256, ROWS / 128, 1), 256, GSMEM>>>(
        abp, wtp + (size_t)3 * E_ * E_, b_out, 0, out, out, out);
}

// round 14
// speedup vs baseline: 1.2159x; 1.2159x over previous
#include <cuda_runtime.h>
#include <cuda_bf16.h>
#include <cstdint>

// Problem constants
#define B_ 8
#define S_ 1024
#define E_ 1024
#define H_ 16
#define D_ 64
#define ROWS (B_ * S_)          // 8192
#define GROUPS (B_ * H_)        // 128
#define GCHUNK (S_ * D_)        // 65536
#define FULL 0xffffffffu

// Scratch (device globals; allocation is forbidden)
__device__ uint32_t g_qb[ROWS * E_];     // Q, tf32 bits, row-major
__device__ uint32_t g_kb[ROWS * E_];     // K, tf32 bits, row-major
__device__ uint32_t g_vb[ROWS * E_];     // V, tf32 bits, row-major
__device__ uint32_t g_attb[ROWS * E_];   // attention out, tf32 bits, A-frag layout
__device__ uint32_t g_x[ROWS * E_];      // hidden_states, tf32 bits, A-frag layout
__device__ uint32_t g_wt[4 * E_ * E_];   // weights, tf32 bits, B-frag layout

__device__ __forceinline__ uint32_t f2tf(float x) {
    uint32_t u;
    asm("cvt.rna.tf32.f32 %0, %1;" : "=r"(u) : "f"(x));
    return u;
}

__device__ __forceinline__ void mma_tf32(float c[4], uint32_t a0, uint32_t a1,
                                         uint32_t a2, uint32_t a3,
                                         uint32_t b0, uint32_t b1) {
    asm volatile(
        "mma.sync.aligned.m16n8k8.row.col.f32.tf32.tf32.f32 "
        "{%0,%1,%2,%3},{%4,%5,%6,%7},{%8,%9},{%0,%1,%2,%3};"
        : "+f"(c[0]), "+f"(c[1]), "+f"(c[2]), "+f"(c[3])
        : "r"(a0), "r"(a1), "r"(a2), "r"(a3), "r"(b0), "r"(b1));
}

__device__ __forceinline__ uint32_t smem_u32(const void* p) {
    uint32_t a;
    asm("{ .reg .u64 t; cvta.to.shared.u64 t, %1; cvt.u32.u64 %0, t; }"
        : "=r"(a) : "l"(p));
    return a;
}

__device__ __forceinline__ void cp16(uint32_t dst, const void* src) {
    asm volatile("cp.async.cg.shared.global [%0], [%1], 16;"
                 :: "r"(dst), "l"(src));
}
#define CPCOMMIT() asm volatile("cp.async.commit_group;" ::: "memory")
#define CPWAIT(n)  asm volatile("cp.async.wait_group %0;" :: "n"(n) : "memory")

// ===========================================================================
// Fragment-order layouts (words of tf32 bits).
// A (activations) [8192 x 1024]:
//   addr = ((m>>7)*64 + (k>>4))*2048 + ((k>>3)&1)*1024 + ((m>>4)&7)*128
//        + ((m&7)*4 + (k&3))*4 + ((k>>2)&1)*2 + ((m>>3)&1)
// B (weights, Bt[n][k] = W[k][n]) [1024 x 1024]:
//   addr = ((n>>7)*64 + (k>>4))*2048 + ((n>>3)&15)*128
//        + ((n&7)*4 + (k&3))*4 + ((k>>3)&1)*2 + ((k>>2)&1)
// ===========================================================================
__device__ __forceinline__ size_t a_addr(int m, int k) {
    return (size_t)((m >> 7) * 64 + (k >> 4)) * 2048
         + ((k >> 3) & 1) * 1024 + ((m >> 4) & 7) * 128
         + ((m & 7) * 4 + (k & 3)) * 4 + ((k >> 2) & 1) * 2 + ((m >> 3) & 1);
}
__device__ __forceinline__ size_t b_addr(int n, int k) {
    return (size_t)((n >> 7) * 64 + (k >> 4)) * 2048
         + ((n >> 3) & 15) * 128
         + ((n & 7) * 4 + (k & 3)) * 4 + ((k >> 3) & 1) * 2 + ((k >> 2) & 1);
}

// ===========================================================================
// Weight W[k][n] -> B-frag layout (tf32). grid (1024, 1, 4), block 256.
// ===========================================================================
__global__ __launch_bounds__(256) void transpose_w(
    const float* __restrict__ w0, const float* __restrict__ w1,
    const float* __restrict__ w2, const float* __restrict__ w3,
    uint32_t* __restrict__ outb)
{
    const float* src = (blockIdx.z == 0) ? w0 : (blockIdx.z == 1) ? w1
                     : (blockIdx.z == 2) ? w2 : w3;
    uint32_t* dst = outb + (size_t)blockIdx.z * E_ * E_;

    const int idx = blockIdx.x * 256 + threadIdx.x;
    const int k  = idx >> 8;
    const int n4 = (idx & 255) * 4;
    float4 v = *(const float4*)(src + (size_t)k * E_ + n4);
    dst[b_addr(n4 + 0, k)] = f2tf(v.x);
    dst[b_addr(n4 + 1, k)] = f2tf(v.y);
    dst[b_addr(n4 + 2, k)] = f2tf(v.z);
    dst[b_addr(n4 + 3, k)] = f2tf(v.w);
}

// ===========================================================================
// hidden_states -> A-frag layout (tf32). grid (8192), block 256.
// ===========================================================================
__global__ __launch_bounds__(256) void convert_x(
    const float* __restrict__ in, uint32_t* __restrict__ out)
{
    const int idx = blockIdx.x * 256 + threadIdx.x;
    const int m  = idx >> 8;
    const int k4 = (idx & 255) * 4;
    float4 v = *(const float4*)(in + (size_t)m * E_ + k4);
    out[a_addr(m, k4 + 0)] = f2tf(v.x);
    out[a_addr(m, k4 + 1)] = f2tf(v.y);
    out[a_addr(m, k4 + 2)] = f2tf(v.z);
    out[a_addr(m, k4 + 3)] = f2tf(v.w);
}

// ===========================================================================
// Pipelined TF32 mma.sync GEMM, fragment-order operands.
// BM=BN=128, BK=16, 256 thr = 8 warps (2x4), warp tile 64x32, 4 stages.
// Mainloop: 12 LDS.128 + 32 HMMA per k16 per warp, conflict-free.
// otf=1 -> tf32-bit row-major output; otf=0 -> fp32 (+bias).
// grid (8, 64, nmat)
// ===========================================================================
#define CHW 2048                 // words per chunk per operand
#define STW (2 * CHW)            // words per stage
#define GSMEM (4 * STW * 4)      // 65536 bytes

__global__ __launch_bounds__(256, 2) void gemm_tc32(
    const uint32_t* __restrict__ A, const uint32_t* __restrict__ Bt_base,
    const float* __restrict__ bias, int otf,
    float* __restrict__ C0, float* __restrict__ C1, float* __restrict__ C2)
{
    extern __shared__ uint32_t sm[];
    const uint32_t sb = smem_u32(sm);

    const int tid  = threadIdx.x;
    const int lane = tid & 31;
    const int wid  = tid >> 5;
    const int wm   = wid >> 2;          // 0..1
    const int wn   = wid & 3;           // 0..3
    const int gid  = lane >> 2;
    const int tig  = lane & 3;

    const int bx = blockIdx.x, by = blockIdx.y, bz = blockIdx.z;
    float* C = (bz == 0) ? C0 : (bz == 1) ? C1 : C2;

    const uint32_t* Apan = A + (size_t)by * 64 * CHW;
    const uint32_t* Bpan = Bt_base + (size_t)bz * E_ * E_ + (size_t)bx * 64 * CHW;

    float acc[4][4][4];
    #pragma unroll
    for (int i = 0; i < 4; i++)
        #pragma unroll
        for (int j = 0; j < 4; j++)
            #pragma unroll
            for (int f = 0; f < 4; f++) acc[i][j][f] = 0.0f;

    const uint32_t dA = sb + (uint32_t)tid * 32;             // tid*8 words
    const uint32_t dB = dA + CHW * 4;

    // ---- prologue: stages 0..2 ----
    #pragma unroll
    for (int s = 0; s < 3; s++) {
        const uint32_t stoff = (uint32_t)(s * STW) * 4;
        const uint32_t* ag = Apan + (size_t)s * CHW + tid * 8;
        const uint32_t* bg = Bpan + (size_t)s * CHW + tid * 8;
        cp16(dA + stoff,      ag);
        cp16(dA + stoff + 16, ag + 4);
        cp16(dB + stoff,      bg);
        cp16(dB + stoff + 16, bg + 4);
        CPCOMMIT();
    }

    for (int c = 0; c < 64; c++) {
        CPWAIT(2);
        __syncthreads();

        if (c + 3 < 64) {
            const uint32_t stoff = (uint32_t)(((c + 3) & 3) * STW) * 4;
            const uint32_t* ag = Apan + (size_t)(c + 3) * CHW + tid * 8;
            const uint32_t* bg = Bpan + (size_t)(c + 3) * CHW + tid * 8;
            cp16(dA + stoff,      ag);
            cp16(dA + stoff + 16, ag + 4);
            cp16(dB + stoff,      bg);
            cp16(dB + stoff + 16, bg + 4);
        }
        CPCOMMIT();

        const uint32_t* As = sm + (size_t)(c & 3) * STW;
        const uint32_t* Bs = As + CHW;

        // B fragments: one LDS.128 per n8-tile covers both k8 steps
        uint4 bq[4];
        #pragma unroll
        for (int j = 0; j < 4; j++)
            bq[j] = *(const uint4*)(Bs + (wn * 4 + j) * 128 + lane * 4);

        #pragma unroll
        for (int s8 = 0; s8 < 2; s8++) {
            uint4 aq[4];
            #pragma unroll
            for (int i = 0; i < 4; i++)
                aq[i] = *(const uint4*)(As + s8 * 1024 + (wm * 4 + i) * 128
                                        + lane * 4);
            #pragma unroll
            for (int i = 0; i < 4; i++)
                #pragma unroll
                for (int j = 0; j < 4; j++) {
                    const uint32_t b0 = s8 ? bq[j].z : bq[j].x;
                    const uint32_t b1 = s8 ? bq[j].w : bq[j].y;
                    mma_tf32(acc[i][j], aq[i].x, aq[i].y, aq[i].z, aq[i].w,
                             b0, b1);
                }
        }
    }

    // ---- epilogue (row-major C) ----
    #pragma unroll
    for (int i = 0; i < 4; i++) {
        const int row0 = by * 128 + wm * 64 + i * 16 + gid;
        #pragma unroll
        for (int j = 0; j < 4; j++) {
            const int col = bx * 128 + wn * 32 + j * 8 + 2 * tig;
            float2 v0, v1;
            if (otf) {
                v0 = make_float2(__uint_as_float(f2tf(acc[i][j][0])),
                                 __uint_as_float(f2tf(acc[i][j][1])));
                v1 = make_float2(__uint_as_float(f2tf(acc[i][j][2])),
                                 __uint_as_float(f2tf(acc[i][j][3])));
            } else {
                float b0 = 0.0f, b1 = 0.0f;
                if (bias != nullptr) { b0 = bias[col]; b1 = bias[col + 1]; }
                v0 = make_float2(acc[i][j][0] + b0, acc[i][j][1] + b1);
                v1 = make_float2(acc[i][j][2] + b0, acc[i][j][3] + b1);
            }
            *(float2*)(C + (size_t)row0 * E_ + col) = v0;
            *(float2*)(C + (size_t)(row0 + 8) * E_ + col) = v1;
        }
    }
}

// ---------------------------------------------------------------------------
// TF32 tensor-core flash attention (r12 proven). Epilogue writes A-frag
// layout words into g_attb for the output projection.
// ---------------------------------------------------------------------------
#define KW 68
#define VW 72
#define KVSTG (64 * KW + 64 * VW)
#define ATT_SMEM (2 * KVSTG * 4)

__global__ __launch_bounds__(128, 3) void attn_mma()
{
    extern __shared__ uint32_t ash[];
    const uint32_t sb = smem_u32(ash);

    const int g    = blockIdx.y;
    const int r0   = blockIdx.x * 64;
    const int tid  = threadIdx.x;
    const int lane = tid & 31;
    const int w    = tid >> 5;
    const int gid  = lane >> 2;
    const int tig  = lane & 3;

    const uint32_t* Qb = g_qb + (size_t)g * GCHUNK;
    const uint32_t* Kb = g_kb + (size_t)g * GCHUNK;
    const uint32_t* Vb = g_vb + (size_t)g * GCHUNK;

    #pragma unroll
    for (int it = 0; it < 8; it++) {
        int slot = tid + it * 128;
        int r  = slot >> 4;
        int c4 = (slot & 15) * 4;
        cp16(sb + (uint32_t)(r * KW + c4) * 4,            Kb + (size_t)r * D_ + c4);
        cp16(sb + (uint32_t)(64 * KW + r * VW + c4) * 4,  Vb + (size_t)r * D_ + c4);
    }
    CPCOMMIT();
    #pragma unroll
    for (int it = 0; it < 8; it++) {
        int slot = tid + it * 128;
        int r  = slot >> 4;
        int c4 = (slot & 15) * 4;
        cp16(sb + (uint32_t)(KVSTG + r * KW + c4) * 4, Qb + (size_t)(r0 + r) * D_ + c4);
    }
    CPCOMMIT();
    CPWAIT(0);
    __syncthreads();

    uint32_t qf[8][4];
    {
        const uint32_t* Qs = ash + KVSTG;
        const int qrow = w * 16;
        #pragma unroll
        for (int kd = 0; kd < 8; kd++) {
            qf[kd][0] = Qs[(qrow + gid) * KW + 8 * kd + tig];
            qf[kd][1] = Qs[(qrow + gid + 8) * KW + 8 * kd + tig];
            qf[kd][2] = Qs[(qrow + gid) * KW + 8 * kd + tig + 4];
            qf[kd][3] = Qs[(qrow + gid + 8) * KW + 8 * kd + tig + 4];
        }
    }
    __syncthreads();

    float oacc[8][4];
    #pragma unroll
    for (int jd = 0; jd < 8; jd++)
        #pragma unroll
        for (int f = 0; f < 4; f++) oacc[jd][f] = 0.0f;

    float m0 = -1e30f, m1 = -1e30f, l0 = 0.0f, l1 = 0.0f;
    const float scale = 0.03125f;

    const int srcbase = lane & ~3;
    const int src0 = srcbase | (tig >> 1);
    const int src2 = src0 + 2;
    const bool hi = tig & 1;

    for (int c = 0; c < 16; c++) {
        if (c > 0) { CPWAIT(0); __syncthreads(); }

        if (c + 1 < 16) {
            const uint32_t dstb = sb + (uint32_t)(((c + 1) & 1) * KVSTG) * 4;
            const int rbase = (c + 1) * 64;
            #pragma unroll
            for (int it = 0; it < 8; it++) {
                int slot = tid + it * 128;
                int r  = slot >> 4;
                int c4 = (slot & 15) * 4;
                cp16(dstb + (uint32_t)(r * KW + c4) * 4,
                     Kb + (size_t)(rbase + r) * D_ + c4);
                cp16(dstb + (uint32_t)(64 * KW + r * VW + c4) * 4,
                     Vb + (size_t)(rbase + r) * D_ + c4);
            }
        }
        CPCOMMIT();

        const uint32_t* Ks = ash + (size_t)(c & 1) * KVSTG;
        const uint32_t* Vs = Ks + 64 * KW;

        float sacc[8][4];
        #pragma unroll
        for (int j = 0; j < 8; j++)
            #pragma unroll
            for (int f = 0; f < 4; f++) sacc[j][f] = 0.0f;

        #pragma unroll
        for (int kd = 0; kd < 8; kd++) {
            uint32_t bf[8][2];
            #pragma unroll
            for (int j = 0; j < 8; j++) {
                bf[j][0] = Ks[(8 * j + gid) * KW + 8 * kd + tig];
                bf[j][1] = Ks[(8 * j + gid) * KW + 8 * kd + tig + 4];
            }
            #pragma unroll
            for (int j = 0; j < 8; j++)
                mma_tf32(sacc[j], qf[kd][0], qf[kd][1], qf[kd][2], qf[kd][3],
                         bf[j][0], bf[j][1]);
        }

        float mx0 = -1e30f, mx1 = -1e30f;
        #pragma unroll
        for (int j = 0; j < 8; j++) {
            sacc[j][0] *= scale; sacc[j][1] *= scale;
            sacc[j][2] *= scale; sacc[j][3] *= scale;
            mx0 = fmaxf(mx0, fmaxf(sacc[j][0], sacc[j][1]));
            mx1 = fmaxf(mx1, fmaxf(sacc[j][2], sacc[j][3]));
        }
        mx0 = fmaxf(mx0, __shfl_xor_sync(FULL, mx0, 1));
        mx0 = fmaxf(mx0, __shfl_xor_sync(FULL, mx0, 2));
        mx1 = fmaxf(mx1, __shfl_xor_sync(FULL, mx1, 1));
        mx1 = fmaxf(mx1, __shfl_xor_sync(FULL, mx1, 2));

        const float nm0 = fmaxf(m0, mx0);
        const float nm1 = fmaxf(m1, mx1);
        const float a0 = __expf(m0 - nm0);
        const float a1 = __expf(m1 - nm1);
        m0 = nm0; m1 = nm1;

        float rs0 = 0.0f, rs1 = 0.0f;
        #pragma unroll
        for (int j = 0; j < 8; j++) {
            sacc[j][0] = __expf(sacc[j][0] - nm0);
            sacc[j][1] = __expf(sacc[j][1] - nm0);
            sacc[j][2] = __expf(sacc[j][2] - nm1);
            sacc[j][3] = __expf(sacc[j][3] - nm1);
            rs0 += sacc[j][0] + sacc[j][1];
            rs1 += sacc[j][2] + sacc[j][3];
        }
        rs0 += __shfl_xor_sync(FULL, rs0, 1);
        rs0 += __shfl_xor_sync(FULL, rs0, 2);
        rs1 += __shfl_xor_sync(FULL, rs1, 1);
        rs1 += __shfl_xor_sync(FULL, rs1, 2);
        l0 = l0 * a0 + rs0;
        l1 = l1 * a1 + rs1;

        #pragma unroll
        for (int jd = 0; jd < 8; jd++) {
            oacc[jd][0] *= a0; oacc[jd][1] *= a0;
            oacc[jd][2] *= a1; oacc[jd][3] *= a1;
        }

        #pragma unroll
        for (int kk = 0; kk < 8; kk++) {
            const float p0 = sacc[kk][0], p1 = sacc[kk][1];
            const float p2 = sacc[kk][2], p3 = sacc[kk][3];
            const float x00 = __shfl_sync(FULL, p0, src0);
            const float x01 = __shfl_sync(FULL, p1, src0);
            const float x20 = __shfl_sync(FULL, p2, src0);
            const float x21 = __shfl_sync(FULL, p3, src0);
            const float y00 = __shfl_sync(FULL, p0, src2);
            const float y01 = __shfl_sync(FULL, p1, src2);
            const float y20 = __shfl_sync(FULL, p2, src2);
            const float y21 = __shfl_sync(FULL, p3, src2);
            const uint32_t af0 = f2tf(hi ? x01 : x00);
            const uint32_t af1 = f2tf(hi ? x21 : x20);
            const uint32_t af2 = f2tf(hi ? y01 : y00);
            const uint32_t af3 = f2tf(hi ? y21 : y20);
            #pragma unroll
            for (int jd = 0; jd < 8; jd++) {
                uint32_t b0 = Vs[(8 * kk + tig) * VW + 8 * jd + gid];
                uint32_t b1 = Vs[(8 * kk + tig + 4) * VW + 8 * jd + gid];
                mma_tf32(oacc[jd], af0, af1, af2, af3, b0, b1);
            }
        }
    }

    // ---- epilogue: normalize, write tf32 bits into A-frag layout ----
    const float inv0 = 1.0f / l0;
    const float inv1 = 1.0f / l1;
    const int b = g >> 4, h = g & 15;
    const int mr0 = b * S_ + r0 + w * 16 + gid;       // row for oacc[][0,1]
    const int mr1 = mr0 + 8;                           // row for oacc[][2,3]
    #pragma unroll
    for (int jd = 0; jd < 8; jd++) {
        const int col = h * D_ + 8 * jd + 2 * tig;
        g_attb[a_addr(mr0, col)]     = f2tf(oacc[jd][0] * inv0);
        g_attb[a_addr(mr0, col + 1)] = f2tf(oacc[jd][1] * inv0);
        g_attb[a_addr(mr1, col)]     = f2tf(oacc[jd][2] * inv1);
        g_attb[a_addr(mr1, col + 1)] = f2tf(oacc[jd][3] * inv1);
    }
}

// ---------------------------------------------------------------------------
extern "C" void kernel_launch(void* const* d_in, const int* in_sizes, int n_in,
                              void* d_out, int out_size)
{
    const float* hs    = (const float*)d_in[0];
    const float* w_q   = (const float*)d_in[1];
    const float* w_k   = (const float*)d_in[2];
    const float* w_v   = (const float*)d_in[3];
    const float* w_out = (const float*)d_in[4];
    const float* b_out = (const float*)d_in[5];
    float* out = (float*)d_out;

    uint32_t *qp, *kp, *vp, *wtp, *xp, *abp;
    cudaGetSymbolAddress((void**)&qp, g_qb);
    cudaGetSymbolAddress((void**)&kp, g_kb);
    cudaGetSymbolAddress((void**)&vp, g_vb);
    cudaGetSymbolAddress((void**)&abp, g_attb);
    cudaGetSymbolAddress((void**)&xp, g_x);
    cudaGetSymbolAddress((void**)&wtp, g_wt);

    cudaFuncSetAttribute(gemm_tc32, cudaFuncAttributeMaxDynamicSharedMemorySize,
                         GSMEM);
    cudaFuncSetAttribute(attn_mma, cudaFuncAttributeMaxDynamicSharedMemorySize,
                         ATT_SMEM);

    // 1. one-time operand conversion into fragment-order layouts
    transpose_w<<<dim3(1024, 1, 4), 256>>>(w_q, w_k, w_v, w_out, wtp);
    convert_x<<<ROWS * E_ / 1024, 256>>>(hs, xp);

    // 2. fused QKV projections (row-major tf32-bit outputs)
    gemm_tc32<<<dim3(8, 64, 3), 256, GSMEM>>>(
        xp, wtp, nullptr, 1, (float*)qp, (float*)kp, (float*)vp);

    // 3. attention (row-major tf32 in, A-frag tf32 bits out)
    attn_mma<<<dim3(S_ / 64, GROUPS), 128, ATT_SMEM>>>();

    // 4. output projection (fp32 out + bias)
    gemm_tc32<<<dim3(8, 64, 1), 256, GSMEM>>>(
        abp, wtp + (size_t)3 * E_ * E_, b_out, 0, out, out, out);
}